// round 15
// baseline (speedup 1.0000x reference)
#include <cuda_runtime.h>
#include <math.h>
#include <cstdint>

#define SLEN   2048
#define BATCH  2
#define DMODEL 1024
#define NHEAD  16
#define DKH    64
#define NROWS  (SLEN * BATCH)   // 4096

// Scratch (device globals: no allocation allowed)
__device__ float g_q[BATCH * NHEAD * SLEN * DKH];   // tf32, pre-scaled log2e/8
__device__ float g_k[BATCH * NHEAD * SLEN * DKH];   // tf32
__device__ float g_v[BATCH * NHEAD * SLEN * DKH];   // tf32
__device__ float g_ctx[NROWS * DMODEL];             // tf32
// tf32-pre-rounded GEMM operands
__device__ float g_qr[NROWS * DMODEL];
__device__ float g_kr[NROWS * DMODEL];
__device__ float g_vr[NROWS * DMODEL];
__device__ float g_wq[DMODEL * DMODEL];
__device__ float g_wk[DMODEL * DMODEL];
__device__ float g_wv[DMODEL * DMODEL];
__device__ float g_wo[DMODEL * DMODEL];

// ---------------------------------------------------------------------------
// Helpers (portable PTX, assembles for plain sm_103)
// ---------------------------------------------------------------------------
__device__ __forceinline__ uint32_t f2tf32(float f) {
    uint32_t u;
    asm("cvt.rna.tf32.f32 %0, %1;" : "=r"(u) : "f"(f));
    return u;
}
__device__ __forceinline__ float rnd_tf32(float f) {
    return __uint_as_float(f2tf32(f));
}
__device__ __forceinline__ float ex2f(float x) {
    float r;
    asm("ex2.approx.f32 %0, %1;" : "=f"(r) : "f"(x));
    return r;
}
__device__ __forceinline__ void mma_tf32(float* c, const uint32_t* a,
                                         uint32_t b0, uint32_t b1) {
    asm volatile(
        "mma.sync.aligned.m16n8k8.row.col.f32.tf32.tf32.f32 "
        "{%0,%1,%2,%3}, {%4,%5,%6,%7}, {%8,%9}, {%0,%1,%2,%3};"
        : "+f"(c[0]), "+f"(c[1]), "+f"(c[2]), "+f"(c[3])
        : "r"(a[0]), "r"(a[1]), "r"(a[2]), "r"(a[3]), "r"(b0), "r"(b1));
}
__device__ __forceinline__ uint32_t smem_u32(const void* p) {
    uint32_t a;
    asm("{ .reg .u64 t; cvta.to.shared.u64 t, %1; cvt.u32.u64 %0, t; }"
        : "=r"(a) : "l"(p));
    return a;
}
__device__ __forceinline__ void cp_async16(uint32_t saddr, const void* gptr) {
    asm volatile("cp.async.cg.shared.global [%0], [%1], 16;"
                 :: "r"(saddr), "l"(gptr) : "memory");
}
#define CP_ASYNC_COMMIT() asm volatile("cp.async.commit_group;" ::: "memory")
template <int N>
__device__ __forceinline__ void cp_async_wait() {
    asm volatile("cp.async.wait_group %0;" :: "n"(N) : "memory");
}
__device__ __forceinline__ void ldsm4(uint32_t* r, uint32_t addr) {
    asm volatile("ldmatrix.sync.aligned.m8n8.x4.shared.b16 {%0,%1,%2,%3}, [%4];"
                 : "=r"(r[0]), "=r"(r[1]), "=r"(r[2]), "=r"(r[3]) : "r"(addr));
}

// ===========================================================================
// Pre-round: tf32-round (rna) the GEMM operands into scratch. Pure stream.
// ===========================================================================
__global__ void __launch_bounds__(256) preround(
    const float* __restrict__ Q, const float* __restrict__ K,
    const float* __restrict__ V, const float* __restrict__ Wq,
    const float* __restrict__ Wk, const float* __restrict__ Wv,
    const float* __restrict__ Wo)
{
    const float* src; float* dst; int n4;
    const int big = NROWS * DMODEL / 4;
    const int wsz = DMODEL * DMODEL / 4;
    switch (blockIdx.y) {
        case 0: src = Q;  dst = g_qr; n4 = big; break;
        case 1: src = K;  dst = g_kr; n4 = big; break;
        case 2: src = V;  dst = g_vr; n4 = big; break;
        case 3: src = Wq; dst = g_wq; n4 = wsz; break;
        case 4: src = Wk; dst = g_wk; n4 = wsz; break;
        case 5: src = Wv; dst = g_wv; n4 = wsz; break;
        default: src = Wo; dst = g_wo; n4 = wsz; break;
    }
    const int stride = gridDim.x * blockDim.x;
    for (int i = blockIdx.x * blockDim.x + threadIdx.x; i < n4; i += stride) {
        float4 x = ((const float4*)src)[i];
        float4 y;
        y.x = rnd_tf32(x.x); y.y = rnd_tf32(x.y);
        y.z = rnd_tf32(x.z); y.w = rnd_tf32(x.w);
        ((float4*)dst)[i] = y;
    }
}

// ===========================================================================
// GEMM: C[M,N] = A[M,K] @ W[N,K]^T + bias (NT). Block 128x128, BK=32.
// 3-stage cp.async pipeline, ONE barrier per chunk.
// Fragment loads via ldmatrix; B fragments double-buffered (ldsm for p+1
// issued before p's mma consume) to hide LDSM latency.
// MODE 0: row-major out; MODE 1: BHSD scatter (rounded);
// MODE 2: BHSD scatter + RoPE (rounded; QSCALE folds log2e/8 into output).
// ===========================================================================
#define GK      1024
#define BKC     32
#define NKIT    (GK / BKC)    // 32
#define SST     36            // 32 + 4 pad: stride%32==4 -> ldsm conflict-free
#define STGW    (128 * SST)
#define GEMM_SMEM_BYTES (3 * 2 * STGW * 4)   // 110592

template <int MODE, bool QSCALE>
__device__ __forceinline__ void gemm_body(
    const float* __restrict__ A, const float* __restrict__ W,
    const float* __restrict__ bias, float* __restrict__ out,
    const float* __restrict__ gcos, const float* __restrict__ gsin,
    uint32_t* gsm)
{
    const uint32_t smb = smem_u32(gsm);
    const int tid = threadIdx.x;
    const int w    = tid >> 5;
    const int lane = tid & 31;
    const int gid  = lane >> 2;
    const int tg   = lane & 3;
    const int wm = w >> 1;
    const int wn = w & 1;
    const int m0 = blockIdx.y * 128;
    const int n0 = blockIdx.x * 128;

    const int srow = tid >> 3;          // 0..31 (4 rows at +32 each)
    const int scol = (tid & 7) * 4;

    const float* abase = A + (size_t)(m0 + srow) * GK + scol;
    const float* wbase = W + (size_t)(n0 + srow) * GK + scol;

    float c[2][8][4];
#pragma unroll
    for (int mt = 0; mt < 2; mt++)
#pragma unroll
        for (int nt = 0; nt < 8; nt++)
#pragma unroll
            for (int j = 0; j < 4; j++) c[mt][nt][j] = 0.0f;

    auto issue = [&](int kc, int st) {
        const uint32_t ab = smb + (uint32_t)(st * 2 * STGW) * 4;
        const uint32_t bb = ab + STGW * 4;
#pragma unroll
        for (int i = 0; i < 4; i++) {
            const int r = srow + 32 * i;
            cp_async16(ab + (r * SST + scol) * 4, abase + (size_t)32 * i * GK + kc);
            cp_async16(bb + (r * SST + scol) * 4, wbase + (size_t)32 * i * GK + kc);
        }
        CP_ASYNC_COMMIT();
    };

    issue(0, 0);
    issue(BKC, 1);

    // ldmatrix per-lane bases (byte offsets within a stage)
    const uint32_t a_off =
        ((wm * 32 + (lane & 7) + ((lane >> 3) & 1) * 8) * SST +
         ((lane >> 4) & 1) * 4) * 4;
    const uint32_t b_off =
        ((wn * 64 + (lane & 7) + ((lane >> 4) & 1) * 8) * SST +
         ((lane >> 3) & 1) * 4) * 4;

    int cst = 0, ist = 2;
    for (int it = 0; it < NKIT; it++) {
        if (it + 1 < NKIT) cp_async_wait<1>();
        else               cp_async_wait<0>();
        __syncthreads();     // chunk `it` visible; stage `ist` free

        if (it + 2 < NKIT) issue((it + 2) * BKC, ist);

        const uint32_t stg = smb + (uint32_t)(cst * 2 * STGW) * 4;
        const uint32_t aA = stg + a_off;
        const uint32_t bB = stg + STGW * 4 + b_off;

#pragma unroll
        for (int ks = 0; ks < 4; ks++) {
            uint32_t a0[4], a1[4];
            ldsm4(a0, aA + ks * 32);
            ldsm4(a1, aA + 16 * SST * 4 + ks * 32);
            uint32_t br[2][4];
            ldsm4(br[0], bB + ks * 32);
#pragma unroll
            for (int p = 0; p < 4; p++) {
                if (p < 3)
                    ldsm4(br[(p + 1) & 1], bB + (p + 1) * (16 * SST * 4) + ks * 32);
                const uint32_t* b = br[p & 1];
                mma_tf32(c[0][2 * p],     a0, b[0], b[1]);
                mma_tf32(c[1][2 * p],     a1, b[0], b[1]);
                mma_tf32(c[0][2 * p + 1], a0, b[2], b[3]);
                mma_tf32(c[1][2 * p + 1], a1, b[2], b[3]);
            }
        }
        cst = (cst == 2) ? 0 : cst + 1;
        ist = (ist == 2) ? 0 : ist + 1;
    }
    __syncthreads();   // smem reuse below (MODE 2)

    if (MODE == 2) {
        // log2e/8 for Q (exact softmax transform into exp2 domain); 1 for K
        const float qs = QSCALE ? 0.18033688011112042f : 1.0f;
        float* rb = (float*)gsm;
        const int s_base = m0 >> 1;
        float4* cs4 = (float4*)rb;
        float4* sn4 = (float4*)(rb + 4096);
#pragma unroll
        for (int i = 0; i < 4; i++) {
            const int idx = i * 256 + tid;
            cs4[idx] = *(const float4*)&gcos[(size_t)s_base * 64 + idx * 4];
            sn4[idx] = *(const float4*)&gsin[(size_t)s_base * 64 + idx * 4];
        }
        __syncthreads();
        const float* cs_s = rb;
        const float* sn_s = rb + 4096;

        const int h = (n0 + wn * 64) >> 6;
#pragma unroll
        for (int mt = 0; mt < 2; mt++) {
            const int rl0 = wm * 32 + mt * 16 + gid;
            const int rl1 = rl0 + 8;
            const int r0 = m0 + rl0;
            const int r1 = m0 + rl1;
            const int sl0 = rl0 >> 1;
            const int sl1 = rl1 >> 1;
            const int s0 = r0 >> 1, b0b = r0 & 1;
            const int s1 = r1 >> 1, b1b = r1 & 1;
            const size_t o0 = (((size_t)(b0b * NHEAD + h)) * SLEN + s0) * DKH;
            const size_t o1 = (((size_t)(b1b * NHEAD + h)) * SLEN + s1) * DKH;
#pragma unroll
            for (int nt = 0; nt < 4; nt++) {
                const int dj = nt * 8 + 2 * tg;
                const int n  = n0 + wn * 64 + dj;
                const float bl0 = bias[n],      bl1 = bias[n + 1];
                const float bh0 = bias[n + 32], bh1 = bias[n + 33];

                const float cA0 = cs_s[sl0 * 64 + dj],      cA1 = cs_s[sl0 * 64 + dj + 1];
                const float sA0 = sn_s[sl0 * 64 + dj],      sA1 = sn_s[sl0 * 64 + dj + 1];
                const float cB0 = cs_s[sl0 * 64 + dj + 32], cB1 = cs_s[sl0 * 64 + dj + 33];
                const float sB0 = sn_s[sl0 * 64 + dj + 32], sB1 = sn_s[sl0 * 64 + dj + 33];
                {
                    const float x10 = c[mt][nt][0] + bl0;
                    const float x11 = c[mt][nt][1] + bl1;
                    const float x20 = c[mt][nt + 4][0] + bh0;
                    const float x21 = c[mt][nt + 4][1] + bh1;
                    float2 lo, hi;
                    lo.x = rnd_tf32((x10 * cA0 - x20 * sA0) * qs);
                    lo.y = rnd_tf32((x11 * cA1 - x21 * sA1) * qs);
                    hi.x = rnd_tf32((x20 * cB0 + x10 * sB0) * qs);
                    hi.y = rnd_tf32((x21 * cB1 + x11 * sB1) * qs);
                    *(float2*)&out[o0 + dj]      = lo;
                    *(float2*)&out[o0 + dj + 32] = hi;
                }
                {
                    const float cC0 = cs_s[sl1 * 64 + dj],      cC1 = cs_s[sl1 * 64 + dj + 1];
                    const float sC0 = sn_s[sl1 * 64 + dj],      sC1 = sn_s[sl1 * 64 + dj + 1];
                    const float cD0 = cs_s[sl1 * 64 + dj + 32], cD1 = cs_s[sl1 * 64 + dj + 33];
                    const float sD0 = sn_s[sl1 * 64 + dj + 32], sD1 = sn_s[sl1 * 64 + dj + 33];
                    const float x10 = c[mt][nt][2] + bl0;
                    const float x11 = c[mt][nt][3] + bl1;
                    const float x20 = c[mt][nt + 4][2] + bh0;
                    const float x21 = c[mt][nt + 4][3] + bh1;
                    float2 lo, hi;
                    lo.x = rnd_tf32((x10 * cC0 - x20 * sC0) * qs);
                    lo.y = rnd_tf32((x11 * cC1 - x21 * sC1) * qs);
                    hi.x = rnd_tf32((x20 * cD0 + x10 * sD0) * qs);
                    hi.y = rnd_tf32((x21 * cD1 + x11 * sD1) * qs);
                    *(float2*)&out[o1 + dj]      = lo;
                    *(float2*)&out[o1 + dj + 32] = hi;
                }
            }
        }
        return;
    }

#pragma unroll
    for (int mt = 0; mt < 2; mt++) {
        const int r0 = m0 + wm * 32 + mt * 16 + gid;
        const int r1 = r0 + 8;
#pragma unroll
        for (int nt = 0; nt < 8; nt++) {
            const int n = n0 + wn * 64 + nt * 8 + 2 * tg;
            float2 v0, v1;
            if (MODE == 0) {
                v0.x = c[mt][nt][0] + bias[n];
                v0.y = c[mt][nt][1] + bias[n + 1];
                v1.x = c[mt][nt][2] + bias[n];
                v1.y = c[mt][nt][3] + bias[n + 1];
                *(float2*)&out[(size_t)r0 * DMODEL + n] = v0;
                *(float2*)&out[(size_t)r1 * DMODEL + n] = v1;
            } else {
                v0.x = rnd_tf32(c[mt][nt][0] + bias[n]);
                v0.y = rnd_tf32(c[mt][nt][1] + bias[n + 1]);
                v1.x = rnd_tf32(c[mt][nt][2] + bias[n]);
                v1.y = rnd_tf32(c[mt][nt][3] + bias[n + 1]);
                const int h  = n >> 6;
                const int dj = n & 63;
                const int s0 = r0 >> 1, b0b = r0 & 1;
                const int s1 = r1 >> 1, b1b = r1 & 1;
                *(float2*)&out[(((size_t)(b0b * NHEAD + h)) * SLEN + s0) * DKH + dj] = v0;
                *(float2*)&out[(((size_t)(b1b * NHEAD + h)) * SLEN + s1) * DKH + dj] = v1;
            }
        }
    }
}

__global__ void __launch_bounds__(256, 2) gemm_qkv(
    const float* qcos, const float* qsin,
    const float* kcos, const float* ksin,
    const float* bq, const float* bk, const float* bv)
{
    extern __shared__ uint32_t gsm[];
    if (blockIdx.z == 0)      gemm_body<2, true >(g_qr, g_wq, bq, g_q, qcos, qsin, gsm);
    else if (blockIdx.z == 1) gemm_body<2, false>(g_kr, g_wk, bk, g_k, kcos, ksin, gsm);
    else                      gemm_body<1, false>(g_vr, g_wv, bv, g_v, nullptr, nullptr, gsm);
}

__global__ void __launch_bounds__(256, 2) gemm_out(
    const float* bias, float* out)
{
    extern __shared__ uint32_t gsm[];
    gemm_body<0, false>(g_ctx, g_wo, bias, out, nullptr, nullptr, gsm);
}

// ===========================================================================
// Causal flash attention, tf32 HMMA, exp2 softmax (Q pre-scaled log2e/8).
// Block = 256 threads (8 warps); 128 q-rows per block (16 per warp).
// 2-stage K/V pipeline, ONE barrier per key tile. (Register-locked form.)
// ===========================================================================
#define KS_STRIDE 68
#define VS_STRIDE 72
#define QTILE     128
#define KS_SZ     (64 * KS_STRIDE)
#define VS_SZ     (64 * VS_STRIDE)
#define QP_OFF    (2 * KS_SZ + 2 * VS_SZ)
#define ATTN_SMEM_BYTES ((QP_OFF + QTILE * KS_STRIDE) * 4)

__global__ void __launch_bounds__(256, 2) attn_tc(
    const float* __restrict__ gq, const float* __restrict__ gk,
    const float* __restrict__ gv, float* __restrict__ ctx)
{
    extern __shared__ uint32_t sm[];
    const uint32_t smb    = smem_u32(sm);
    const uint32_t ks_u   = smb;
    const uint32_t vs_u   = smb + 2 * KS_SZ * 4;
    const uint32_t qp_u   = smb + QP_OFF * 4;
    uint32_t* VsB = sm + 2 * KS_SZ;
    uint32_t* QP  = sm + QP_OFF;

    const int tid  = threadIdx.x;
    const int w    = tid >> 5;
    const int lane = tid & 31;
    const int gid  = lane >> 2;
    const int tg   = lane & 3;
    const int qt = (int)gridDim.x - 1 - (int)blockIdx.x;
    const int bh = blockIdx.y;
    const int b  = bh / NHEAD;
    const int h  = bh % NHEAD;
    const size_t base = (size_t)bh * SLEN * DKH;
    const int q0   = qt * QTILE;
    const int qrow = w * 16;

    const int fcK = tid >> 4;
    const int fd4 = (tid & 15) * 4;

    const uint32_t a_base = qp_u +
        ((qrow + (lane & 7) + ((lane >> 3) & 1) * 8) * KS_STRIDE +
         ((lane >> 4) & 1) * 4) * 4;
    const uint32_t kb_base =
        (((lane & 7) + ((lane >> 4) & 1) * 8) * KS_STRIDE +
         ((lane >> 3) & 1) * 4) * 4;

#pragma unroll
    for (int i = 0; i < 8; i++) {
        const int idx = i * 256 + tid;
        const int r  = idx >> 4;
        const int d4 = (idx & 15) * 4;
        cp_async16(qp_u + (r * KS_STRIDE + d4) * 4,
                   gq + base + (size_t)(q0 + r) * 64 + d4);
    }
#pragma unroll
    for (int i = 0; i < 4; i++) {
        const int cK = fcK + i * 16;
        const size_t goff = base + (size_t)cK * 64 + fd4;
        cp_async16(ks_u + (cK * KS_STRIDE + fd4) * 4, gk + goff);
        cp_async16(vs_u + (cK * VS_STRIDE + fd4) * 4, gv + goff);
    }
    CP_ASYNC_COMMIT();
    cp_async_wait<0>();
    __syncthreads();

    uint32_t qa[8][4];
#pragma unroll
    for (int ks = 0; ks < 8; ks++) ldsm4(qa[ks], a_base + ks * 32);

    float o[8][4];
#pragma unroll
    for (int nt = 0; nt < 8; nt++)
#pragma unroll
        for (int j = 0; j < 4; j++) o[nt][j] = 0.0f;
    float m0r = -1e30f, m1r = -1e30f, l0 = 0.0f, l1 = 0.0f;

    const int r0g = q0 + qrow + gid;
    const int r1g = r0g + 8;
    const int wrow_max = q0 + qrow + 15;

    const int nkt = 2 * qt + 2;
    for (int kt = 0; kt < nkt; kt++) {
        const int k0g = kt * 64;
        const int cur = kt & 1;

        if (kt > 0) {
            cp_async_wait<0>();   // tile kt landed
            __syncthreads();      // all warps done with stage cur^1
        }
        if (kt + 1 < nkt) {       // refill the stage freed by tile kt-1
            const size_t nb = base + (size_t)(k0g + 64) * 64;
            const uint32_t ksn = ks_u + (cur ^ 1) * KS_SZ * 4;
            const uint32_t vsn = vs_u + (cur ^ 1) * VS_SZ * 4;
#pragma unroll
            for (int i = 0; i < 4; i++) {
                const int cK = fcK + i * 16;
                const size_t goff = nb + (size_t)cK * 64 + fd4;
                cp_async16(ksn + (cK * KS_STRIDE + fd4) * 4, gk + goff);
                cp_async16(vsn + (cK * VS_STRIDE + fd4) * 4, gv + goff);
            }
            CP_ASYNC_COMMIT();
        }

        if (k0g <= wrow_max) {
            const uint32_t kb = ks_u + cur * KS_SZ * 4 + kb_base;
            const uint32_t* Vs = VsB + cur * VS_SZ;

            float sc[8][4];
#pragma unroll
            for (int nt = 0; nt < 8; nt++)
#pragma unroll
                for (int j = 0; j < 4; j++) sc[nt][j] = 0.0f;
#pragma unroll
            for (int ks = 0; ks < 8; ks++) {
#pragma unroll
                for (int p = 0; p < 4; p++) {
                    uint32_t br[4];
                    ldsm4(br, kb + p * (16 * KS_STRIDE * 4) + ks * 32);
                    mma_tf32(sc[2 * p],     qa[ks], br[0], br[1]);
                    mma_tf32(sc[2 * p + 1], qa[ks], br[2], br[3]);
                }
            }

            // causal mask only (scale folded into Q)
            if (kt >= 2 * qt) {
#pragma unroll
                for (int nt = 0; nt < 8; nt++) {
                    const int col = k0g + nt * 8 + 2 * tg;
                    if (col     > r0g) sc[nt][0] = -1e30f;
                    if (col + 1 > r0g) sc[nt][1] = -1e30f;
                    if (col     > r1g) sc[nt][2] = -1e30f;
                    if (col + 1 > r1g) sc[nt][3] = -1e30f;
                }
            }

            float mx0 = -1e30f, mx1 = -1e30f;
#pragma unroll
            for (int nt = 0; nt < 8; nt++) {
                mx0 = fmaxf(mx0, fmaxf(sc[nt][0], sc[nt][1]));
                mx1 = fmaxf(mx1, fmaxf(sc[nt][2], sc[nt][3]));
            }
            mx0 = fmaxf(mx0, __shfl_xor_sync(0xffffffffu, mx0, 1));
            mx0 = fmaxf(mx0, __shfl_xor_sync(0xffffffffu, mx0, 2));
            mx1 = fmaxf(mx1, __shfl_xor_sync(0xffffffffu, mx1, 1));
            mx1 = fmaxf(mx1, __shfl_xor_sync(0xffffffffu, mx1, 2));

            const float mn0 = fmaxf(m0r, mx0);
            const float mn1 = fmaxf(m1r, mx1);
            const float al0 = ex2f(m0r - mn0);
            const float al1 = ex2f(m1r - mn1);
            m0r = mn0; m1r = mn1;

            float rs0 = 0.0f, rs1 = 0.0f;
            const int pbase = (qrow + gid) * KS_STRIDE + 2 * tg;
#pragma unroll
            for (int nt = 0; nt < 8; nt++) {
                float p0 = ex2f(sc[nt][0] - mn0);
                float p1 = ex2f(sc[nt][1] - mn0);
                float p2 = ex2f(sc[nt][2] - mn1);
                float p3 = ex2f(sc[nt][3] - mn1);
                rs0 += p0 + p1;
                rs1 += p2 + p3;
                uint2 u01; u01.x = f2tf32(p0); u01.y = f2tf32(p1);
                uint2 u23; u23.x = f2tf32(p2); u23.y = f2tf32(p3);
                *(uint2*)&QP[pbase + nt * 8]                 = u01;
                *(uint2*)&QP[pbase + nt * 8 + 8 * KS_STRIDE] = u23;
            }
            rs0 += __shfl_xor_sync(0xffffffffu, rs0, 1);
            rs0 += __shfl_xor_sync(0xffffffffu, rs0, 2);
            rs1 += __shfl_xor_sync(0xffffffffu, rs1, 1);
            rs1 += __shfl_xor_sync(0xffffffffu, rs1, 2);
            l0 = l0 * al0 + rs0;
            l1 = l1 * al1 + rs1;

#pragma unroll
            for (int nt = 0; nt < 8; nt++) {
                o[nt][0] *= al0; o[nt][1] *= al0;
                o[nt][2] *= al1; o[nt][3] *= al1;
            }
            __syncwarp();

#pragma unroll
            for (int ks = 0; ks < 8; ks++) {
                uint32_t pa[4];
                ldsm4(pa, a_base + ks * 32);
#pragma unroll
                for (int nt = 0; nt < 8; nt++) {
                    uint32_t b0 = Vs[(ks * 8 + tg) * VS_STRIDE + nt * 8 + gid];
                    uint32_t b1 = Vs[(ks * 8 + tg + 4) * VS_STRIDE + nt * 8 + gid];
                    mma_tf32(o[nt], pa, b0, b1);
                }
            }
        }
    }

    const float inv0 = 1.0f / l0;
    const float inv1 = 1.0f / l1;
#pragma unroll
    for (int nt = 0; nt < 8; nt++) {
        const int col = h * 64 + nt * 8 + 2 * tg;
        float2 v0, v1;
        v0.x = rnd_tf32(o[nt][0] * inv0); v0.y = rnd_tf32(o[nt][1] * inv0);
        v1.x = rnd_tf32(o[nt][2] * inv1); v1.y = rnd_tf32(o[nt][3] * inv1);
        *(float2*)&ctx[((size_t)r0g * BATCH + b) * DMODEL + col] = v0;
        *(float2*)&ctx[((size_t)r1g * BATCH + b) * DMODEL + col] = v1;
    }
}

// ---------------------------------------------------------------------------
extern "C" void kernel_launch(void* const* d_in, const int* in_sizes, int n_in,
                              void* d_out, int out_size)
{
    (void)in_sizes; (void)n_in; (void)out_size;
    const float* Q    = (const float*)d_in[0];
    const float* K    = (const float*)d_in[1];
    const float* V    = (const float*)d_in[2];
    const float* W_q  = (const float*)d_in[3];
    const float* b_q  = (const float*)d_in[4];
    const float* W_k  = (const float*)d_in[5];
    const float* b_k  = (const float*)d_in[6];
    const float* W_v  = (const float*)d_in[7];
    const float* b_v  = (const float*)d_in[8];
    const float* W_o  = (const float*)d_in[9];
    const float* b_o  = (const float*)d_in[10];
    const float* qcos = (const float*)d_in[11];
    const float* qsin = (const float*)d_in[12];
    const float* kcos = (const float*)d_in[13];
    const float* ksin = (const float*)d_in[14];
    float* out = (float*)d_out;

    float *gq, *gk, *gv, *gctx;
    cudaGetSymbolAddress((void**)&gq,   g_q);
    cudaGetSymbolAddress((void**)&gk,   g_k);
    cudaGetSymbolAddress((void**)&gv,   g_v);
    cudaGetSymbolAddress((void**)&gctx, g_ctx);

    cudaFuncSetAttribute(attn_tc,
                         cudaFuncAttributeMaxDynamicSharedMemorySize,
                         ATTN_SMEM_BYTES);
    cudaFuncSetAttribute(gemm_qkv,
                         cudaFuncAttributeMaxDynamicSharedMemorySize,
                         GEMM_SMEM_BYTES);
    cudaFuncSetAttribute(gemm_out,
                         cudaFuncAttributeMaxDynamicSharedMemorySize,
                         GEMM_SMEM_BYTES);

    dim3 pgrid(1024, 7);
    preround<<<pgrid, 256>>>(Q, K, V, W_q, W_k, W_v, W_o);

    dim3 qkv_grid(DMODEL / 128, NROWS / 128, 3);   // (8, 32, 3)
    gemm_qkv<<<qkv_grid, 256, GEMM_SMEM_BYTES>>>(
        qcos, qsin, kcos, ksin, b_q, b_k, b_v);

    dim3 agrid(SLEN / QTILE, BATCH * NHEAD);       // (16, 32)
    attn_tc<<<agrid, 256, ATTN_SMEM_BYTES>>>(gq, gk, gv, gctx);

    dim3 ogrid(DMODEL / 128, NROWS / 128);         // (8, 32)
    gemm_out<<<ogrid, 256, GEMM_SMEM_BYTES>>>(b_o, out);
}

// round 16
// speedup vs baseline: 1.0077x; 1.0077x over previous
#include <cuda_runtime.h>
#include <math.h>
#include <cstdint>

#define SLEN   2048
#define BATCH  2
#define DMODEL 1024
#define NHEAD  16
#define DKH    64
#define NROWS  (SLEN * BATCH)   // 4096

// Scratch (device globals: no allocation allowed)
__device__ float g_q[BATCH * NHEAD * SLEN * DKH];   // tf32, pre-scaled log2e/8
__device__ float g_k[BATCH * NHEAD * SLEN * DKH];   // tf32
__device__ float g_v[BATCH * NHEAD * SLEN * DKH];   // tf32
__device__ float g_ctx[NROWS * DMODEL];             // tf32
// tf32-pre-rounded GEMM operands
__device__ float g_qr[NROWS * DMODEL];
__device__ float g_kr[NROWS * DMODEL];
__device__ float g_vr[NROWS * DMODEL];
__device__ float g_wq[DMODEL * DMODEL];
__device__ float g_wk[DMODEL * DMODEL];
__device__ float g_wv[DMODEL * DMODEL];
__device__ float g_wo[DMODEL * DMODEL];

// ---------------------------------------------------------------------------
// Helpers (portable PTX, assembles for plain sm_103)
// ---------------------------------------------------------------------------
__device__ __forceinline__ uint32_t f2tf32(float f) {
    uint32_t u;
    asm("cvt.rna.tf32.f32 %0, %1;" : "=r"(u) : "f"(f));
    return u;
}
__device__ __forceinline__ float rnd_tf32(float f) {
    return __uint_as_float(f2tf32(f));
}
__device__ __forceinline__ float ex2f(float x) {
    float r;
    asm("ex2.approx.f32 %0, %1;" : "=f"(r) : "f"(x));
    return r;
}
__device__ __forceinline__ void mma_tf32(float* c, const uint32_t* a,
                                         uint32_t b0, uint32_t b1) {
    asm volatile(
        "mma.sync.aligned.m16n8k8.row.col.f32.tf32.tf32.f32 "
        "{%0,%1,%2,%3}, {%4,%5,%6,%7}, {%8,%9}, {%0,%1,%2,%3};"
        : "+f"(c[0]), "+f"(c[1]), "+f"(c[2]), "+f"(c[3])
        : "r"(a[0]), "r"(a[1]), "r"(a[2]), "r"(a[3]), "r"(b0), "r"(b1));
}
__device__ __forceinline__ uint32_t smem_u32(const void* p) {
    uint32_t a;
    asm("{ .reg .u64 t; cvta.to.shared.u64 t, %1; cvt.u32.u64 %0, t; }"
        : "=r"(a) : "l"(p));
    return a;
}
__device__ __forceinline__ void cp_async16(uint32_t saddr, const void* gptr) {
    asm volatile("cp.async.cg.shared.global [%0], [%1], 16;"
                 :: "r"(saddr), "l"(gptr) : "memory");
}
#define CP_ASYNC_COMMIT() asm volatile("cp.async.commit_group;" ::: "memory")
template <int N>
__device__ __forceinline__ void cp_async_wait() {
    asm volatile("cp.async.wait_group %0;" :: "n"(N) : "memory");
}
__device__ __forceinline__ void ldsm4(uint32_t* r, uint32_t addr) {
    asm volatile("ldmatrix.sync.aligned.m8n8.x4.shared.b16 {%0,%1,%2,%3}, [%4];"
                 : "=r"(r[0]), "=r"(r[1]), "=r"(r[2]), "=r"(r[3]) : "r"(addr));
}

// ===========================================================================
// Pre-round: tf32-round (rna) the GEMM operands into scratch. Pure stream.
// ===========================================================================
__global__ void __launch_bounds__(256) preround(
    const float* __restrict__ Q, const float* __restrict__ K,
    const float* __restrict__ V, const float* __restrict__ Wq,
    const float* __restrict__ Wk, const float* __restrict__ Wv,
    const float* __restrict__ Wo)
{
    const float* src; float* dst; int n4;
    const int big = NROWS * DMODEL / 4;
    const int wsz = DMODEL * DMODEL / 4;
    switch (blockIdx.y) {
        case 0: src = Q;  dst = g_qr; n4 = big; break;
        case 1: src = K;  dst = g_kr; n4 = big; break;
        case 2: src = V;  dst = g_vr; n4 = big; break;
        case 3: src = Wq; dst = g_wq; n4 = wsz; break;
        case 4: src = Wk; dst = g_wk; n4 = wsz; break;
        case 5: src = Wv; dst = g_wv; n4 = wsz; break;
        default: src = Wo; dst = g_wo; n4 = wsz; break;
    }
    const int stride = gridDim.x * blockDim.x;
    for (int i = blockIdx.x * blockDim.x + threadIdx.x; i < n4; i += stride) {
        float4 x = ((const float4*)src)[i];
        float4 y;
        y.x = rnd_tf32(x.x); y.y = rnd_tf32(x.y);
        y.z = rnd_tf32(x.z); y.w = rnd_tf32(x.w);
        ((float4*)dst)[i] = y;
    }
}

// ===========================================================================
// GEMM: C[M,N] = A[M,K] @ W[N,K]^T + bias (NT). Block 128x128, BK=32.
// 3-stage cp.async pipeline, ONE barrier per chunk.
// ALL fragment loads via ldmatrix (SST=36 -> conflict-free 8-row phases).
// (Round-14 inner loop — the B-frag double-buffer was a measured regression.)
// MODE 0: row-major out; MODE 1: BHSD scatter (rounded);
// MODE 2: BHSD scatter + RoPE (rounded; QSCALE folds log2e/8 into output).
// ===========================================================================
#define GK      1024
#define BKC     32
#define NKIT    (GK / BKC)    // 32
#define SST     36            // 32 + 4 pad: stride%32==4 -> ldsm conflict-free
#define STGW    (128 * SST)
#define GEMM_SMEM_BYTES (3 * 2 * STGW * 4)   // 110592

template <int MODE, bool QSCALE>
__device__ __forceinline__ void gemm_body(
    const float* __restrict__ A, const float* __restrict__ W,
    const float* __restrict__ bias, float* __restrict__ out,
    const float* __restrict__ gcos, const float* __restrict__ gsin,
    uint32_t* gsm)
{
    const uint32_t smb = smem_u32(gsm);
    const int tid = threadIdx.x;
    const int w    = tid >> 5;
    const int lane = tid & 31;
    const int gid  = lane >> 2;
    const int tg   = lane & 3;
    const int wm = w >> 1;
    const int wn = w & 1;
    const int m0 = blockIdx.y * 128;
    const int n0 = blockIdx.x * 128;

    const int srow = tid >> 3;          // 0..31 (4 rows at +32 each)
    const int scol = (tid & 7) * 4;

    const float* abase = A + (size_t)(m0 + srow) * GK + scol;
    const float* wbase = W + (size_t)(n0 + srow) * GK + scol;

    float c[2][8][4];
#pragma unroll
    for (int mt = 0; mt < 2; mt++)
#pragma unroll
        for (int nt = 0; nt < 8; nt++)
#pragma unroll
            for (int j = 0; j < 4; j++) c[mt][nt][j] = 0.0f;

    auto issue = [&](int kc, int st) {
        const uint32_t ab = smb + (uint32_t)(st * 2 * STGW) * 4;
        const uint32_t bb = ab + STGW * 4;
#pragma unroll
        for (int i = 0; i < 4; i++) {
            const int r = srow + 32 * i;
            cp_async16(ab + (r * SST + scol) * 4, abase + (size_t)32 * i * GK + kc);
            cp_async16(bb + (r * SST + scol) * 4, wbase + (size_t)32 * i * GK + kc);
        }
        CP_ASYNC_COMMIT();
    };

    issue(0, 0);
    issue(BKC, 1);

    // ldmatrix per-lane bases (byte offsets within a stage)
    const uint32_t a_off =
        ((wm * 32 + (lane & 7) + ((lane >> 3) & 1) * 8) * SST +
         ((lane >> 4) & 1) * 4) * 4;
    const uint32_t b_off =
        ((wn * 64 + (lane & 7) + ((lane >> 4) & 1) * 8) * SST +
         ((lane >> 3) & 1) * 4) * 4;

    int cst = 0, ist = 2;
    for (int it = 0; it < NKIT; it++) {
        if (it + 1 < NKIT) cp_async_wait<1>();
        else               cp_async_wait<0>();
        __syncthreads();     // chunk `it` visible; stage `ist` free

        if (it + 2 < NKIT) issue((it + 2) * BKC, ist);

        const uint32_t stg = smb + (uint32_t)(cst * 2 * STGW) * 4;
        const uint32_t aA = stg + a_off;
        const uint32_t bB = stg + STGW * 4 + b_off;

#pragma unroll
        for (int ks = 0; ks < 4; ks++) {
            uint32_t a0[4], a1[4];
            ldsm4(a0, aA + ks * 32);
            ldsm4(a1, aA + 16 * SST * 4 + ks * 32);
#pragma unroll
            for (int p = 0; p < 4; p++) {
                uint32_t br[4];
                ldsm4(br, bB + p * (16 * SST * 4) + ks * 32);
                mma_tf32(c[0][2 * p],     a0, br[0], br[1]);
                mma_tf32(c[1][2 * p],     a1, br[0], br[1]);
                mma_tf32(c[0][2 * p + 1], a0, br[2], br[3]);
                mma_tf32(c[1][2 * p + 1], a1, br[2], br[3]);
            }
        }
        cst = (cst == 2) ? 0 : cst + 1;
        ist = (ist == 2) ? 0 : ist + 1;
    }
    __syncthreads();   // smem reuse below (MODE 2)

    if (MODE == 2) {
        // log2e/8 for Q (exact softmax transform into exp2 domain); 1 for K
        const float qs = QSCALE ? 0.18033688011112042f : 1.0f;
        float* rb = (float*)gsm;
        const int s_base = m0 >> 1;
        float4* cs4 = (float4*)rb;
        float4* sn4 = (float4*)(rb + 4096);
#pragma unroll
        for (int i = 0; i < 4; i++) {
            const int idx = i * 256 + tid;
            cs4[idx] = *(const float4*)&gcos[(size_t)s_base * 64 + idx * 4];
            sn4[idx] = *(const float4*)&gsin[(size_t)s_base * 64 + idx * 4];
        }
        __syncthreads();
        const float* cs_s = rb;
        const float* sn_s = rb + 4096;

        const int h = (n0 + wn * 64) >> 6;
#pragma unroll
        for (int mt = 0; mt < 2; mt++) {
            const int rl0 = wm * 32 + mt * 16 + gid;
            const int rl1 = rl0 + 8;
            const int r0 = m0 + rl0;
            const int r1 = m0 + rl1;
            const int sl0 = rl0 >> 1;
            const int sl1 = rl1 >> 1;
            const int s0 = r0 >> 1, b0b = r0 & 1;
            const int s1 = r1 >> 1, b1b = r1 & 1;
            const size_t o0 = (((size_t)(b0b * NHEAD + h)) * SLEN + s0) * DKH;
            const size_t o1 = (((size_t)(b1b * NHEAD + h)) * SLEN + s1) * DKH;
#pragma unroll
            for (int nt = 0; nt < 4; nt++) {
                const int dj = nt * 8 + 2 * tg;
                const int n  = n0 + wn * 64 + dj;
                const float bl0 = bias[n],      bl1 = bias[n + 1];
                const float bh0 = bias[n + 32], bh1 = bias[n + 33];

                const float cA0 = cs_s[sl0 * 64 + dj],      cA1 = cs_s[sl0 * 64 + dj + 1];
                const float sA0 = sn_s[sl0 * 64 + dj],      sA1 = sn_s[sl0 * 64 + dj + 1];
                const float cB0 = cs_s[sl0 * 64 + dj + 32], cB1 = cs_s[sl0 * 64 + dj + 33];
                const float sB0 = sn_s[sl0 * 64 + dj + 32], sB1 = sn_s[sl0 * 64 + dj + 33];
                {
                    const float x10 = c[mt][nt][0] + bl0;
                    const float x11 = c[mt][nt][1] + bl1;
                    const float x20 = c[mt][nt + 4][0] + bh0;
                    const float x21 = c[mt][nt + 4][1] + bh1;
                    float2 lo, hi;
                    lo.x = rnd_tf32((x10 * cA0 - x20 * sA0) * qs);
                    lo.y = rnd_tf32((x11 * cA1 - x21 * sA1) * qs);
                    hi.x = rnd_tf32((x20 * cB0 + x10 * sB0) * qs);
                    hi.y = rnd_tf32((x21 * cB1 + x11 * sB1) * qs);
                    *(float2*)&out[o0 + dj]      = lo;
                    *(float2*)&out[o0 + dj + 32] = hi;
                }
                {
                    const float cC0 = cs_s[sl1 * 64 + dj],      cC1 = cs_s[sl1 * 64 + dj + 1];
                    const float sC0 = sn_s[sl1 * 64 + dj],      sC1 = sn_s[sl1 * 64 + dj + 1];
                    const float cD0 = cs_s[sl1 * 64 + dj + 32], cD1 = cs_s[sl1 * 64 + dj + 33];
                    const float sD0 = sn_s[sl1 * 64 + dj + 32], sD1 = sn_s[sl1 * 64 + dj + 33];
                    const float x10 = c[mt][nt][2] + bl0;
                    const float x11 = c[mt][nt][3] + bl1;
                    const float x20 = c[mt][nt + 4][2] + bh0;
                    const float x21 = c[mt][nt + 4][3] + bh1;
                    float2 lo, hi;
                    lo.x = rnd_tf32((x10 * cC0 - x20 * sC0) * qs);
                    lo.y = rnd_tf32((x11 * cC1 - x21 * sC1) * qs);
                    hi.x = rnd_tf32((x20 * cD0 + x10 * sD0) * qs);
                    hi.y = rnd_tf32((x21 * cD1 + x11 * sD1) * qs);
                    *(float2*)&out[o1 + dj]      = lo;
                    *(float2*)&out[o1 + dj + 32] = hi;
                }
            }
        }
        return;
    }

#pragma unroll
    for (int mt = 0; mt < 2; mt++) {
        const int r0 = m0 + wm * 32 + mt * 16 + gid;
        const int r1 = r0 + 8;
#pragma unroll
        for (int nt = 0; nt < 8; nt++) {
            const int n = n0 + wn * 64 + nt * 8 + 2 * tg;
            float2 v0, v1;
            if (MODE == 0) {
                v0.x = c[mt][nt][0] + bias[n];
                v0.y = c[mt][nt][1] + bias[n + 1];
                v1.x = c[mt][nt][2] + bias[n];
                v1.y = c[mt][nt][3] + bias[n + 1];
                *(float2*)&out[(size_t)r0 * DMODEL + n] = v0;
                *(float2*)&out[(size_t)r1 * DMODEL + n] = v1;
            } else {
                v0.x = rnd_tf32(c[mt][nt][0] + bias[n]);
                v0.y = rnd_tf32(c[mt][nt][1] + bias[n + 1]);
                v1.x = rnd_tf32(c[mt][nt][2] + bias[n]);
                v1.y = rnd_tf32(c[mt][nt][3] + bias[n + 1]);
                const int h  = n >> 6;
                const int dj = n & 63;
                const int s0 = r0 >> 1, b0b = r0 & 1;
                const int s1 = r1 >> 1, b1b = r1 & 1;
                *(float2*)&out[(((size_t)(b0b * NHEAD + h)) * SLEN + s0) * DKH + dj] = v0;
                *(float2*)&out[(((size_t)(b1b * NHEAD + h)) * SLEN + s1) * DKH + dj] = v1;
            }
        }
    }
}

__global__ void __launch_bounds__(256, 2) gemm_qkv(
    const float* qcos, const float* qsin,
    const float* kcos, const float* ksin,
    const float* bq, const float* bk, const float* bv)
{
    extern __shared__ uint32_t gsm[];
    if (blockIdx.z == 0)      gemm_body<2, true >(g_qr, g_wq, bq, g_q, qcos, qsin, gsm);
    else if (blockIdx.z == 1) gemm_body<2, false>(g_kr, g_wk, bk, g_k, kcos, ksin, gsm);
    else                      gemm_body<1, false>(g_vr, g_wv, bv, g_v, nullptr, nullptr, gsm);
}

__global__ void __launch_bounds__(256, 2) gemm_out(
    const float* bias, float* out)
{
    extern __shared__ uint32_t gsm[];
    gemm_body<0, false>(g_ctx, g_wo, bias, out, nullptr, nullptr, gsm);
}

// ===========================================================================
// Causal flash attention, tf32 HMMA, exp2 softmax (Q pre-scaled log2e/8).
// Block = 256 threads (8 warps); 128 q-rows per block (16 per warp).
// 2-stage K/V pipeline with SPLIT commit groups: QK waits only on K;
// V wait deferred past softmax (extra slack for the V load).
// ===========================================================================
#define KS_STRIDE 68
#define VS_STRIDE 72
#define QTILE     128
#define KS_SZ     (64 * KS_STRIDE)
#define VS_SZ     (64 * VS_STRIDE)
#define QP_OFF    (2 * KS_SZ + 2 * VS_SZ)
#define ATTN_SMEM_BYTES ((QP_OFF + QTILE * KS_STRIDE) * 4)

__global__ void __launch_bounds__(256, 2) attn_tc(
    const float* __restrict__ gq, const float* __restrict__ gk,
    const float* __restrict__ gv, float* __restrict__ ctx)
{
    extern __shared__ uint32_t sm[];
    const uint32_t smb    = smem_u32(sm);
    const uint32_t ks_u   = smb;
    const uint32_t vs_u   = smb + 2 * KS_SZ * 4;
    const uint32_t qp_u   = smb + QP_OFF * 4;
    uint32_t* VsB = sm + 2 * KS_SZ;
    uint32_t* QP  = sm + QP_OFF;

    const int tid  = threadIdx.x;
    const int w    = tid >> 5;
    const int lane = tid & 31;
    const int gid  = lane >> 2;
    const int tg   = lane & 3;
    const int qt = (int)gridDim.x - 1 - (int)blockIdx.x;
    const int bh = blockIdx.y;
    const int b  = bh / NHEAD;
    const int h  = bh % NHEAD;
    const size_t base = (size_t)bh * SLEN * DKH;
    const int q0   = qt * QTILE;
    const int qrow = w * 16;

    const int fcK = tid >> 4;
    const int fd4 = (tid & 15) * 4;

    const uint32_t a_base = qp_u +
        ((qrow + (lane & 7) + ((lane >> 3) & 1) * 8) * KS_STRIDE +
         ((lane >> 4) & 1) * 4) * 4;
    const uint32_t kb_base =
        (((lane & 7) + ((lane >> 4) & 1) * 8) * KS_STRIDE +
         ((lane >> 3) & 1) * 4) * 4;

    // prologue: [Q + K0] group, then [V0] group
#pragma unroll
    for (int i = 0; i < 8; i++) {
        const int idx = i * 256 + tid;
        const int r  = idx >> 4;
        const int d4 = (idx & 15) * 4;
        cp_async16(qp_u + (r * KS_STRIDE + d4) * 4,
                   gq + base + (size_t)(q0 + r) * 64 + d4);
    }
#pragma unroll
    for (int i = 0; i < 4; i++) {
        const int cK = fcK + i * 16;
        cp_async16(ks_u + (cK * KS_STRIDE + fd4) * 4,
                   gk + base + (size_t)cK * 64 + fd4);
    }
    CP_ASYNC_COMMIT();
#pragma unroll
    for (int i = 0; i < 4; i++) {
        const int cK = fcK + i * 16;
        cp_async16(vs_u + (cK * VS_STRIDE + fd4) * 4,
                   gv + base + (size_t)cK * 64 + fd4);
    }
    CP_ASYNC_COMMIT();

    // wait for Q+K0 (V0 may still be in flight)
    cp_async_wait<1>();
    __syncthreads();

    uint32_t qa[8][4];
#pragma unroll
    for (int ks = 0; ks < 8; ks++) ldsm4(qa[ks], a_base + ks * 32);

    float o[8][4];
#pragma unroll
    for (int nt = 0; nt < 8; nt++)
#pragma unroll
        for (int j = 0; j < 4; j++) o[nt][j] = 0.0f;
    float m0r = -1e30f, m1r = -1e30f, l0 = 0.0f, l1 = 0.0f;

    const int r0g = q0 + qrow + gid;
    const int r1g = r0g + 8;
    const int wrow_max = q0 + qrow + 15;

    const int nkt = 2 * qt + 2;
    for (int kt = 0; kt < nkt; kt++) {
        const int k0g = kt * 64;
        const int cur = kt & 1;
        const bool have_next = (kt + 1 < nkt);

        if (kt > 0) {
            // outstanding: [V(kt-1)]?, [K(kt)], [V(kt)] -> wait<1>: K(kt) done
            cp_async_wait<1>();
            __syncthreads();      // all warps done with stage cur^1
        }
        if (have_next) {          // issue K(kt+1) into freed K stage
            const uint32_t ksn = ks_u + (cur ^ 1) * KS_SZ * 4;
            const size_t kb_g = base + (size_t)(k0g + 64) * 64;
#pragma unroll
            for (int i = 0; i < 4; i++) {
                const int cK = fcK + i * 16;
                cp_async16(ksn + (cK * KS_STRIDE + fd4) * 4,
                           gk + kb_g + (size_t)cK * 64 + fd4);
            }
            CP_ASYNC_COMMIT();
        }

        if (k0g <= wrow_max) {
            const uint32_t kb = ks_u + cur * KS_SZ * 4 + kb_base;
            const uint32_t* Vs = VsB + cur * VS_SZ;

            float sc[8][4];
#pragma unroll
            for (int nt = 0; nt < 8; nt++)
#pragma unroll
                for (int j = 0; j < 4; j++) sc[nt][j] = 0.0f;
#pragma unroll
            for (int ks = 0; ks < 8; ks++) {
#pragma unroll
                for (int p = 0; p < 4; p++) {
                    uint32_t br[4];
                    ldsm4(br, kb + p * (16 * KS_STRIDE * 4) + ks * 32);
                    mma_tf32(sc[2 * p],     qa[ks], br[0], br[1]);
                    mma_tf32(sc[2 * p + 1], qa[ks], br[2], br[3]);
                }
            }

            // causal mask only (scale folded into Q)
            if (kt >= 2 * qt) {
#pragma unroll
                for (int nt = 0; nt < 8; nt++) {
                    const int col = k0g + nt * 8 + 2 * tg;
                    if (col     > r0g) sc[nt][0] = -1e30f;
                    if (col + 1 > r0g) sc[nt][1] = -1e30f;
                    if (col     > r1g) sc[nt][2] = -1e30f;
                    if (col + 1 > r1g) sc[nt][3] = -1e30f;
                }
            }

            float mx0 = -1e30f, mx1 = -1e30f;
#pragma unroll
            for (int nt = 0; nt < 8; nt++) {
                mx0 = fmaxf(mx0, fmaxf(sc[nt][0], sc[nt][1]));
                mx1 = fmaxf(mx1, fmaxf(sc[nt][2], sc[nt][3]));
            }
            mx0 = fmaxf(mx0, __shfl_xor_sync(0xffffffffu, mx0, 1));
            mx0 = fmaxf(mx0, __shfl_xor_sync(0xffffffffu, mx0, 2));
            mx1 = fmaxf(mx1, __shfl_xor_sync(0xffffffffu, mx1, 1));
            mx1 = fmaxf(mx1, __shfl_xor_sync(0xffffffffu, mx1, 2));

            const float mn0 = fmaxf(m0r, mx0);
            const float mn1 = fmaxf(m1r, mx1);
            const float al0 = ex2f(m0r - mn0);
            const float al1 = ex2f(m1r - mn1);
            m0r = mn0; m1r = mn1;

            float rs0 = 0.0f, rs1 = 0.0f;
            const int pbase = (qrow + gid) * KS_STRIDE + 2 * tg;
#pragma unroll
            for (int nt = 0; nt < 8; nt++) {
                float p0 = ex2f(sc[nt][0] - mn0);
                float p1 = ex2f(sc[nt][1] - mn0);
                float p2 = ex2f(sc[nt][2] - mn1);
                float p3 = ex2f(sc[nt][3] - mn1);
                rs0 += p0 + p1;
                rs1 += p2 + p3;
                uint2 u01; u01.x = f2tf32(p0); u01.y = f2tf32(p1);
                uint2 u23; u23.x = f2tf32(p2); u23.y = f2tf32(p3);
                *(uint2*)&QP[pbase + nt * 8]                 = u01;
                *(uint2*)&QP[pbase + nt * 8 + 8 * KS_STRIDE] = u23;
            }
            rs0 += __shfl_xor_sync(0xffffffffu, rs0, 1);
            rs0 += __shfl_xor_sync(0xffffffffu, rs0, 2);
            rs1 += __shfl_xor_sync(0xffffffffu, rs1, 1);
            rs1 += __shfl_xor_sync(0xffffffffu, rs1, 2);
            l0 = l0 * al0 + rs0;
            l1 = l1 * al1 + rs1;

#pragma unroll
            for (int nt = 0; nt < 8; nt++) {
                o[nt][0] *= al0; o[nt][1] *= al0;
                o[nt][2] *= al1; o[nt][3] *= al1;
            }
            __syncwarp();

            // V(kt) needed now: outstanding = [V(kt)], [K(kt+1)]? ->
            // wait<1> when K(kt+1) was committed, else wait<0>.
            if (have_next) cp_async_wait<1>();
            else           cp_async_wait<0>();

#pragma unroll
            for (int ks = 0; ks < 8; ks++) {
                uint32_t pa[4];
                ldsm4(pa, a_base + ks * 32);
#pragma unroll
                for (int nt = 0; nt < 8; nt++) {
                    uint32_t b0 = Vs[(ks * 8 + tg) * VS_STRIDE + nt * 8 + gid];
                    uint32_t b1 = Vs[(ks * 8 + tg + 4) * VS_STRIDE + nt * 8 + gid];
                    mma_tf32(o[nt], pa, b0, b1);
                }
            }
        }

        if (have_next) {          // issue V(kt+1) into freed V stage
            const uint32_t vsn = vs_u + (cur ^ 1) * VS_SZ * 4;
            const size_t vb_g = base + (size_t)(k0g + 64) * 64;
#pragma unroll
            for (int i = 0; i < 4; i++) {
                const int cK = fcK + i * 16;
                cp_async16(vsn + (cK * VS_STRIDE + fd4) * 4,
                           gv + vb_g + (size_t)cK * 64 + fd4);
            }
            CP_ASYNC_COMMIT();
        }
    }

    const float inv0 = 1.0f / l0;
    const float inv1 = 1.0f / l1;
#pragma unroll
    for (int nt = 0; nt < 8; nt++) {
        const int col = h * 64 + nt * 8 + 2 * tg;
        float2 v0, v1;
        v0.x = rnd_tf32(o[nt][0] * inv0); v0.y = rnd_tf32(o[nt][1] * inv0);
        v1.x = rnd_tf32(o[nt][2] * inv1); v1.y = rnd_tf32(o[nt][3] * inv1);
        *(float2*)&ctx[((size_t)r0g * BATCH + b) * DMODEL + col] = v0;
        *(float2*)&ctx[((size_t)r1g * BATCH + b) * DMODEL + col] = v1;
    }
}

// ---------------------------------------------------------------------------
extern "C" void kernel_launch(void* const* d_in, const int* in_sizes, int n_in,
                              void* d_out, int out_size)
{
    (void)in_sizes; (void)n_in; (void)out_size;
    const float* Q    = (const float*)d_in[0];
    const float* K    = (const float*)d_in[1];
    const float* V    = (const float*)d_in[2];
    const float* W_q  = (const float*)d_in[3];
    const float* b_q  = (const float*)d_in[4];
    const float* W_k  = (const float*)d_in[5];
    const float* b_k  = (const float*)d_in[6];
    const float* W_v  = (const float*)d_in[7];
    const float* b_v  = (const float*)d_in[8];
    const float* W_o  = (const float*)d_in[9];
    const float* b_o  = (const float*)d_in[10];
    const float* qcos = (const float*)d_in[11];
    const float* qsin = (const float*)d_in[12];
    const float* kcos = (const float*)d_in[13];
    const float* ksin = (const float*)d_in[14];
    float* out = (float*)d_out;

    float *gq, *gk, *gv, *gctx;
    cudaGetSymbolAddress((void**)&gq,   g_q);
    cudaGetSymbolAddress((void**)&gk,   g_k);
    cudaGetSymbolAddress((void**)&gv,   g_v);
    cudaGetSymbolAddress((void**)&gctx, g_ctx);

    cudaFuncSetAttribute(attn_tc,
                         cudaFuncAttributeMaxDynamicSharedMemorySize,
                         ATTN_SMEM_BYTES);
    cudaFuncSetAttribute(gemm_qkv,
                         cudaFuncAttributeMaxDynamicSharedMemorySize,
                         GEMM_SMEM_BYTES);
    cudaFuncSetAttribute(gemm_out,
                         cudaFuncAttributeMaxDynamicSharedMemorySize,
                         GEMM_SMEM_BYTES);

    dim3 pgrid(1024, 7);
    preround<<<pgrid, 256>>>(Q, K, V, W_q, W_k, W_v, W_o);

    dim3 qkv_grid(DMODEL / 128, NROWS / 128, 3);   // (8, 32, 3)
    gemm_qkv<<<qkv_grid, 256, GEMM_SMEM_BYTES>>>(
        qcos, qsin, kcos, ksin, b_q, b_k, b_v);

    dim3 agrid(SLEN / QTILE, BATCH * NHEAD);       // (16, 32)
    attn_tc<<<agrid, 256, ATTN_SMEM_BYTES>>>(gq, gk, gv, gctx);

    dim3 ogrid(DMODEL / 128, NROWS / 128);         // (8, 32)
    gemm_out<<<ogrid, 256, GEMM_SMEM_BYTES>>>(b_o, out);
}

// round 17
// speedup vs baseline: 1.0537x; 1.0456x over previous
#include <cuda_runtime.h>
#include <math.h>
#include <cstdint>

#define SLEN   2048
#define BATCH  2
#define DMODEL 1024
#define NHEAD  16
#define DKH    64
#define NROWS  (SLEN * BATCH)   // 4096

// Scratch (device globals: no allocation allowed)
__device__ float g_q[BATCH * NHEAD * SLEN * DKH];   // tf32, pre-scaled log2e/8
__device__ float g_k[BATCH * NHEAD * SLEN * DKH];   // tf32
__device__ float g_v[BATCH * NHEAD * SLEN * DKH];   // tf32
__device__ float g_ctx[NROWS * DMODEL];             // tf32
// tf32-pre-rounded weights (B operands)
__device__ float g_wq[DMODEL * DMODEL];
__device__ float g_wk[DMODEL * DMODEL];
__device__ float g_wv[DMODEL * DMODEL];
__device__ float g_wo[DMODEL * DMODEL];

// ---------------------------------------------------------------------------
// Helpers (portable PTX, assembles for plain sm_103)
// ---------------------------------------------------------------------------
__device__ __forceinline__ uint32_t f2tf32(float f) {
    uint32_t u;
    asm("cvt.rna.tf32.f32 %0, %1;" : "=r"(u) : "f"(f));
    return u;
}
__device__ __forceinline__ float rnd_tf32(float f) {
    return __uint_as_float(f2tf32(f));
}
__device__ __forceinline__ float ex2f(float x) {
    float r;
    asm("ex2.approx.f32 %0, %1;" : "=f"(r) : "f"(x));
    return r;
}
__device__ __forceinline__ void mma_tf32(float* c, const uint32_t* a,
                                         uint32_t b0, uint32_t b1) {
    asm volatile(
        "mma.sync.aligned.m16n8k8.row.col.f32.tf32.tf32.f32 "
        "{%0,%1,%2,%3}, {%4,%5,%6,%7}, {%8,%9}, {%0,%1,%2,%3};"
        : "+f"(c[0]), "+f"(c[1]), "+f"(c[2]), "+f"(c[3])
        : "r"(a[0]), "r"(a[1]), "r"(a[2]), "r"(a[3]), "r"(b0), "r"(b1));
}
__device__ __forceinline__ uint32_t smem_u32(const void* p) {
    uint32_t a;
    asm("{ .reg .u64 t; cvta.to.shared.u64 t, %1; cvt.u32.u64 %0, t; }"
        : "=r"(a) : "l"(p));
    return a;
}
__device__ __forceinline__ void cp_async16(uint32_t saddr, const void* gptr) {
    asm volatile("cp.async.cg.shared.global [%0], [%1], 16;"
                 :: "r"(saddr), "l"(gptr) : "memory");
}
#define CP_ASYNC_COMMIT() asm volatile("cp.async.commit_group;" ::: "memory")
template <int N>
__device__ __forceinline__ void cp_async_wait() {
    asm volatile("cp.async.wait_group %0;" :: "n"(N) : "memory");
}
__device__ __forceinline__ void ldsm4(uint32_t* r, uint32_t addr) {
    asm volatile("ldmatrix.sync.aligned.m8n8.x4.shared.b16 {%0,%1,%2,%3}, [%4];"
                 : "=r"(r[0]), "=r"(r[1]), "=r"(r[2]), "=r"(r[3]) : "r"(addr));
}

// ===========================================================================
// Pre-round: tf32-round (rna) the 4 weight matrices only. Pure stream.
// (Q/K/V/ctx A-operands are fed raw: HMMA ignores the low 13 mantissa bits,
//  i.e. round-toward-zero on the A operand — ~2.4e-4 systematic, acceptable.)
// ===========================================================================
__global__ void __launch_bounds__(256) preround_w(
    const float* __restrict__ Wq, const float* __restrict__ Wk,
    const float* __restrict__ Wv, const float* __restrict__ Wo)
{
    const float* src; float* dst;
    switch (blockIdx.y) {
        case 0:  src = Wq; dst = g_wq; break;
        case 1:  src = Wk; dst = g_wk; break;
        case 2:  src = Wv; dst = g_wv; break;
        default: src = Wo; dst = g_wo; break;
    }
    const int n4 = DMODEL * DMODEL / 4;
    const int stride = gridDim.x * blockDim.x;
    for (int i = blockIdx.x * blockDim.x + threadIdx.x; i < n4; i += stride) {
        float4 x = ((const float4*)src)[i];
        float4 y;
        y.x = rnd_tf32(x.x); y.y = rnd_tf32(x.y);
        y.z = rnd_tf32(x.z); y.w = rnd_tf32(x.w);
        ((float4*)dst)[i] = y;
    }
}

// ===========================================================================
// GEMM: C[M,N] = A[M,K] @ W[N,K]^T + bias (NT). Block 128x128, BK=32.
// 3-stage cp.async pipeline, ONE barrier per chunk.
// ALL fragment loads via ldmatrix (SST=36 -> conflict-free 8-row phases).
// A operand raw fp32 (HW truncates); W pre-rounded.
// MODE 0: row-major out; MODE 1: BHSD scatter (rounded);
// MODE 2: BHSD scatter + RoPE (rounded; QSCALE folds log2e/8 into output).
// ===========================================================================
#define GK      1024
#define BKC     32
#define NKIT    (GK / BKC)    // 32
#define SST     36            // 32 + 4 pad: stride%32==4 -> ldsm conflict-free
#define STGW    (128 * SST)
#define GEMM_SMEM_BYTES (3 * 2 * STGW * 4)   // 110592

template <int MODE, bool QSCALE>
__device__ __forceinline__ void gemm_body(
    const float* __restrict__ A, const float* __restrict__ W,
    const float* __restrict__ bias, float* __restrict__ out,
    const float* __restrict__ gcos, const float* __restrict__ gsin,
    uint32_t* gsm)
{
    const uint32_t smb = smem_u32(gsm);
    const int tid = threadIdx.x;
    const int w    = tid >> 5;
    const int lane = tid & 31;
    const int gid  = lane >> 2;
    const int tg   = lane & 3;
    const int wm = w >> 1;
    const int wn = w & 1;
    const int m0 = blockIdx.y * 128;
    const int n0 = blockIdx.x * 128;

    const int srow = tid >> 3;          // 0..31 (4 rows at +32 each)
    const int scol = (tid & 7) * 4;

    const float* abase = A + (size_t)(m0 + srow) * GK + scol;
    const float* wbase = W + (size_t)(n0 + srow) * GK + scol;

    float c[2][8][4];
#pragma unroll
    for (int mt = 0; mt < 2; mt++)
#pragma unroll
        for (int nt = 0; nt < 8; nt++)
#pragma unroll
            for (int j = 0; j < 4; j++) c[mt][nt][j] = 0.0f;

    auto issue = [&](int kc, int st) {
        const uint32_t ab = smb + (uint32_t)(st * 2 * STGW) * 4;
        const uint32_t bb = ab + STGW * 4;
#pragma unroll
        for (int i = 0; i < 4; i++) {
            const int r = srow + 32 * i;
            cp_async16(ab + (r * SST + scol) * 4, abase + (size_t)32 * i * GK + kc);
            cp_async16(bb + (r * SST + scol) * 4, wbase + (size_t)32 * i * GK + kc);
        }
        CP_ASYNC_COMMIT();
    };

    issue(0, 0);
    issue(BKC, 1);

    // ldmatrix per-lane bases (byte offsets within a stage)
    const uint32_t a_off =
        ((wm * 32 + (lane & 7) + ((lane >> 3) & 1) * 8) * SST +
         ((lane >> 4) & 1) * 4) * 4;
    const uint32_t b_off =
        ((wn * 64 + (lane & 7) + ((lane >> 4) & 1) * 8) * SST +
         ((lane >> 3) & 1) * 4) * 4;

    int cst = 0, ist = 2;
    for (int it = 0; it < NKIT; it++) {
        if (it + 1 < NKIT) cp_async_wait<1>();
        else               cp_async_wait<0>();
        __syncthreads();     // chunk `it` visible; stage `ist` free

        if (it + 2 < NKIT) issue((it + 2) * BKC, ist);

        const uint32_t stg = smb + (uint32_t)(cst * 2 * STGW) * 4;
        const uint32_t aA = stg + a_off;
        const uint32_t bB = stg + STGW * 4 + b_off;

#pragma unroll
        for (int ks = 0; ks < 4; ks++) {
            uint32_t a0[4], a1[4];
            ldsm4(a0, aA + ks * 32);
            ldsm4(a1, aA + 16 * SST * 4 + ks * 32);
#pragma unroll
            for (int p = 0; p < 4; p++) {
                uint32_t br[4];
                ldsm4(br, bB + p * (16 * SST * 4) + ks * 32);
                mma_tf32(c[0][2 * p],     a0, br[0], br[1]);
                mma_tf32(c[1][2 * p],     a1, br[0], br[1]);
                mma_tf32(c[0][2 * p + 1], a0, br[2], br[3]);
                mma_tf32(c[1][2 * p + 1], a1, br[2], br[3]);
            }
        }
        cst = (cst == 2) ? 0 : cst + 1;
        ist = (ist == 2) ? 0 : ist + 1;
    }
    __syncthreads();   // smem reuse below (MODE 2)

    if (MODE == 2) {
        // log2e/8 for Q (exact softmax transform into exp2 domain); 1 for K
        const float qs = QSCALE ? 0.18033688011112042f : 1.0f;
        float* rb = (float*)gsm;
        const int s_base = m0 >> 1;
        float4* cs4 = (float4*)rb;
        float4* sn4 = (float4*)(rb + 4096);
#pragma unroll
        for (int i = 0; i < 4; i++) {
            const int idx = i * 256 + tid;
            cs4[idx] = *(const float4*)&gcos[(size_t)s_base * 64 + idx * 4];
            sn4[idx] = *(const float4*)&gsin[(size_t)s_base * 64 + idx * 4];
        }
        __syncthreads();
        const float* cs_s = rb;
        const float* sn_s = rb + 4096;

        const int h = (n0 + wn * 64) >> 6;
#pragma unroll
        for (int mt = 0; mt < 2; mt++) {
            const int rl0 = wm * 32 + mt * 16 + gid;
            const int rl1 = rl0 + 8;
            const int r0 = m0 + rl0;
            const int r1 = m0 + rl1;
            const int sl0 = rl0 >> 1;
            const int sl1 = rl1 >> 1;
            const int s0 = r0 >> 1, b0b = r0 & 1;
            const int s1 = r1 >> 1, b1b = r1 & 1;
            const size_t o0 = (((size_t)(b0b * NHEAD + h)) * SLEN + s0) * DKH;
            const size_t o1 = (((size_t)(b1b * NHEAD + h)) * SLEN + s1) * DKH;
#pragma unroll
            for (int nt = 0; nt < 4; nt++) {
                const int dj = nt * 8 + 2 * tg;
                const int n  = n0 + wn * 64 + dj;
                const float bl0 = bias[n],      bl1 = bias[n + 1];
                const float bh0 = bias[n + 32], bh1 = bias[n + 33];

                const float cA0 = cs_s[sl0 * 64 + dj],      cA1 = cs_s[sl0 * 64 + dj + 1];
                const float sA0 = sn_s[sl0 * 64 + dj],      sA1 = sn_s[sl0 * 64 + dj + 1];
                const float cB0 = cs_s[sl0 * 64 + dj + 32], cB1 = cs_s[sl0 * 64 + dj + 33];
                const float sB0 = sn_s[sl0 * 64 + dj + 32], sB1 = sn_s[sl0 * 64 + dj + 33];
                {
                    const float x10 = c[mt][nt][0] + bl0;
                    const float x11 = c[mt][nt][1] + bl1;
                    const float x20 = c[mt][nt + 4][0] + bh0;
                    const float x21 = c[mt][nt + 4][1] + bh1;
                    float2 lo, hi;
                    lo.x = rnd_tf32((x10 * cA0 - x20 * sA0) * qs);
                    lo.y = rnd_tf32((x11 * cA1 - x21 * sA1) * qs);
                    hi.x = rnd_tf32((x20 * cB0 + x10 * sB0) * qs);
                    hi.y = rnd_tf32((x21 * cB1 + x11 * sB1) * qs);
                    *(float2*)&out[o0 + dj]      = lo;
                    *(float2*)&out[o0 + dj + 32] = hi;
                }
                {
                    const float cC0 = cs_s[sl1 * 64 + dj],      cC1 = cs_s[sl1 * 64 + dj + 1];
                    const float sC0 = sn_s[sl1 * 64 + dj],      sC1 = sn_s[sl1 * 64 + dj + 1];
                    const float cD0 = cs_s[sl1 * 64 + dj + 32], cD1 = cs_s[sl1 * 64 + dj + 33];
                    const float sD0 = sn_s[sl1 * 64 + dj + 32], sD1 = sn_s[sl1 * 64 + dj + 33];
                    const float x10 = c[mt][nt][2] + bl0;
                    const float x11 = c[mt][nt][3] + bl1;
                    const float x20 = c[mt][nt + 4][2] + bh0;
                    const float x21 = c[mt][nt + 4][3] + bh1;
                    float2 lo, hi;
                    lo.x = rnd_tf32((x10 * cC0 - x20 * sC0) * qs);
                    lo.y = rnd_tf32((x11 * cC1 - x21 * sC1) * qs);
                    hi.x = rnd_tf32((x20 * cD0 + x10 * sD0) * qs);
                    hi.y = rnd_tf32((x21 * cD1 + x11 * sD1) * qs);
                    *(float2*)&out[o1 + dj]      = lo;
                    *(float2*)&out[o1 + dj + 32] = hi;
                }
            }
        }
        return;
    }

#pragma unroll
    for (int mt = 0; mt < 2; mt++) {
        const int r0 = m0 + wm * 32 + mt * 16 + gid;
        const int r1 = r0 + 8;
#pragma unroll
        for (int nt = 0; nt < 8; nt++) {
            const int n = n0 + wn * 64 + nt * 8 + 2 * tg;
            float2 v0, v1;
            if (MODE == 0) {
                v0.x = c[mt][nt][0] + bias[n];
                v0.y = c[mt][nt][1] + bias[n + 1];
                v1.x = c[mt][nt][2] + bias[n];
                v1.y = c[mt][nt][3] + bias[n + 1];
                *(float2*)&out[(size_t)r0 * DMODEL + n] = v0;
                *(float2*)&out[(size_t)r1 * DMODEL + n] = v1;
            } else {
                v0.x = rnd_tf32(c[mt][nt][0] + bias[n]);
                v0.y = rnd_tf32(c[mt][nt][1] + bias[n + 1]);
                v1.x = rnd_tf32(c[mt][nt][2] + bias[n]);
                v1.y = rnd_tf32(c[mt][nt][3] + bias[n + 1]);
                const int h  = n >> 6;
                const int dj = n & 63;
                const int s0 = r0 >> 1, b0b = r0 & 1;
                const int s1 = r1 >> 1, b1b = r1 & 1;
                *(float2*)&out[(((size_t)(b0b * NHEAD + h)) * SLEN + s0) * DKH + dj] = v0;
                *(float2*)&out[(((size_t)(b1b * NHEAD + h)) * SLEN + s1) * DKH + dj] = v1;
            }
        }
    }
}

__global__ void __launch_bounds__(256, 2) gemm_qkv(
    const float* Q, const float* K, const float* V,
    const float* qcos, const float* qsin,
    const float* kcos, const float* ksin,
    const float* bq, const float* bk, const float* bv)
{
    extern __shared__ uint32_t gsm[];
    if (blockIdx.z == 0)      gemm_body<2, true >(Q, g_wq, bq, g_q, qcos, qsin, gsm);
    else if (blockIdx.z == 1) gemm_body<2, false>(K, g_wk, bk, g_k, kcos, ksin, gsm);
    else                      gemm_body<1, false>(V, g_wv, bv, g_v, nullptr, nullptr, gsm);
}

__global__ void __launch_bounds__(256, 2) gemm_out(
    const float* bias, float* out)
{
    extern __shared__ uint32_t gsm[];
    gemm_body<0, false>(g_ctx, g_wo, bias, out, nullptr, nullptr, gsm);
}

// ===========================================================================
// Causal flash attention, tf32 HMMA, exp2 softmax (Q pre-scaled log2e/8).
// Block = 256 threads (8 warps); 128 q-rows per block (16 per warp).
// 2-stage K/V pipeline, ONE barrier per key tile. (Round-14 form.)
// ===========================================================================
#define KS_STRIDE 68
#define VS_STRIDE 72
#define QTILE     128
#define KS_SZ     (64 * KS_STRIDE)
#define VS_SZ     (64 * VS_STRIDE)
#define QP_OFF    (2 * KS_SZ + 2 * VS_SZ)
#define ATTN_SMEM_BYTES ((QP_OFF + QTILE * KS_STRIDE) * 4)

__global__ void __launch_bounds__(256, 2) attn_tc(
    const float* __restrict__ gq, const float* __restrict__ gk,
    const float* __restrict__ gv, float* __restrict__ ctx)
{
    extern __shared__ uint32_t sm[];
    const uint32_t smb    = smem_u32(sm);
    const uint32_t ks_u   = smb;
    const uint32_t vs_u   = smb + 2 * KS_SZ * 4;
    const uint32_t qp_u   = smb + QP_OFF * 4;
    uint32_t* VsB = sm + 2 * KS_SZ;
    uint32_t* QP  = sm + QP_OFF;

    const int tid  = threadIdx.x;
    const int w    = tid >> 5;
    const int lane = tid & 31;
    const int gid  = lane >> 2;
    const int tg   = lane & 3;
    const int qt = (int)gridDim.x - 1 - (int)blockIdx.x;
    const int bh = blockIdx.y;
    const int b  = bh / NHEAD;
    const int h  = bh % NHEAD;
    const size_t base = (size_t)bh * SLEN * DKH;
    const int q0   = qt * QTILE;
    const int qrow = w * 16;

    const int fcK = tid >> 4;
    const int fd4 = (tid & 15) * 4;

    const uint32_t a_base = qp_u +
        ((qrow + (lane & 7) + ((lane >> 3) & 1) * 8) * KS_STRIDE +
         ((lane >> 4) & 1) * 4) * 4;
    const uint32_t kb_base =
        (((lane & 7) + ((lane >> 4) & 1) * 8) * KS_STRIDE +
         ((lane >> 3) & 1) * 4) * 4;

#pragma unroll
    for (int i = 0; i < 8; i++) {
        const int idx = i * 256 + tid;
        const int r  = idx >> 4;
        const int d4 = (idx & 15) * 4;
        cp_async16(qp_u + (r * KS_STRIDE + d4) * 4,
                   gq + base + (size_t)(q0 + r) * 64 + d4);
    }
#pragma unroll
    for (int i = 0; i < 4; i++) {
        const int cK = fcK + i * 16;
        const size_t goff = base + (size_t)cK * 64 + fd4;
        cp_async16(ks_u + (cK * KS_STRIDE + fd4) * 4, gk + goff);
        cp_async16(vs_u + (cK * VS_STRIDE + fd4) * 4, gv + goff);
    }
    CP_ASYNC_COMMIT();
    cp_async_wait<0>();
    __syncthreads();

    uint32_t qa[8][4];
#pragma unroll
    for (int ks = 0; ks < 8; ks++) ldsm4(qa[ks], a_base + ks * 32);

    float o[8][4];
#pragma unroll
    for (int nt = 0; nt < 8; nt++)
#pragma unroll
        for (int j = 0; j < 4; j++) o[nt][j] = 0.0f;
    float m0r = -1e30f, m1r = -1e30f, l0 = 0.0f, l1 = 0.0f;

    const int r0g = q0 + qrow + gid;
    const int r1g = r0g + 8;
    const int wrow_max = q0 + qrow + 15;

    const int nkt = 2 * qt + 2;
    for (int kt = 0; kt < nkt; kt++) {
        const int k0g = kt * 64;
        const int cur = kt & 1;

        if (kt > 0) {
            cp_async_wait<0>();   // tile kt landed
            __syncthreads();      // all warps done with stage cur^1
        }
        if (kt + 1 < nkt) {       // refill the stage freed by tile kt-1
            const size_t nb = base + (size_t)(k0g + 64) * 64;
            const uint32_t ksn = ks_u + (cur ^ 1) * KS_SZ * 4;
            const uint32_t vsn = vs_u + (cur ^ 1) * VS_SZ * 4;
#pragma unroll
            for (int i = 0; i < 4; i++) {
                const int cK = fcK + i * 16;
                const size_t goff = nb + (size_t)cK * 64 + fd4;
                cp_async16(ksn + (cK * KS_STRIDE + fd4) * 4, gk + goff);
                cp_async16(vsn + (cK * VS_STRIDE + fd4) * 4, gv + goff);
            }
            CP_ASYNC_COMMIT();
        }

        if (k0g <= wrow_max) {
            const uint32_t kb = ks_u + cur * KS_SZ * 4 + kb_base;
            const uint32_t* Vs = VsB + cur * VS_SZ;

            float sc[8][4];
#pragma unroll
            for (int nt = 0; nt < 8; nt++)
#pragma unroll
                for (int j = 0; j < 4; j++) sc[nt][j] = 0.0f;
#pragma unroll
            for (int ks = 0; ks < 8; ks++) {
#pragma unroll
                for (int p = 0; p < 4; p++) {
                    uint32_t br[4];
                    ldsm4(br, kb + p * (16 * KS_STRIDE * 4) + ks * 32);
                    mma_tf32(sc[2 * p],     qa[ks], br[0], br[1]);
                    mma_tf32(sc[2 * p + 1], qa[ks], br[2], br[3]);
                }
            }

            // causal mask only (scale folded into Q)
            if (kt >= 2 * qt) {
#pragma unroll
                for (int nt = 0; nt < 8; nt++) {
                    const int col = k0g + nt * 8 + 2 * tg;
                    if (col     > r0g) sc[nt][0] = -1e30f;
                    if (col + 1 > r0g) sc[nt][1] = -1e30f;
                    if (col     > r1g) sc[nt][2] = -1e30f;
                    if (col + 1 > r1g) sc[nt][3] = -1e30f;
                }
            }

            float mx0 = -1e30f, mx1 = -1e30f;
#pragma unroll
            for (int nt = 0; nt < 8; nt++) {
                mx0 = fmaxf(mx0, fmaxf(sc[nt][0], sc[nt][1]));
                mx1 = fmaxf(mx1, fmaxf(sc[nt][2], sc[nt][3]));
            }
            mx0 = fmaxf(mx0, __shfl_xor_sync(0xffffffffu, mx0, 1));
            mx0 = fmaxf(mx0, __shfl_xor_sync(0xffffffffu, mx0, 2));
            mx1 = fmaxf(mx1, __shfl_xor_sync(0xffffffffu, mx1, 1));
            mx1 = fmaxf(mx1, __shfl_xor_sync(0xffffffffu, mx1, 2));

            const float mn0 = fmaxf(m0r, mx0);
            const float mn1 = fmaxf(m1r, mx1);
            const float al0 = ex2f(m0r - mn0);
            const float al1 = ex2f(m1r - mn1);
            m0r = mn0; m1r = mn1;

            float rs0 = 0.0f, rs1 = 0.0f;
            const int pbase = (qrow + gid) * KS_STRIDE + 2 * tg;
#pragma unroll
            for (int nt = 0; nt < 8; nt++) {
                float p0 = ex2f(sc[nt][0] - mn0);
                float p1 = ex2f(sc[nt][1] - mn0);
                float p2 = ex2f(sc[nt][2] - mn1);
                float p3 = ex2f(sc[nt][3] - mn1);
                rs0 += p0 + p1;
                rs1 += p2 + p3;
                uint2 u01; u01.x = f2tf32(p0); u01.y = f2tf32(p1);
                uint2 u23; u23.x = f2tf32(p2); u23.y = f2tf32(p3);
                *(uint2*)&QP[pbase + nt * 8]                 = u01;
                *(uint2*)&QP[pbase + nt * 8 + 8 * KS_STRIDE] = u23;
            }
            rs0 += __shfl_xor_sync(0xffffffffu, rs0, 1);
            rs0 += __shfl_xor_sync(0xffffffffu, rs0, 2);
            rs1 += __shfl_xor_sync(0xffffffffu, rs1, 1);
            rs1 += __shfl_xor_sync(0xffffffffu, rs1, 2);
            l0 = l0 * al0 + rs0;
            l1 = l1 * al1 + rs1;

#pragma unroll
            for (int nt = 0; nt < 8; nt++) {
                o[nt][0] *= al0; o[nt][1] *= al0;
                o[nt][2] *= al1; o[nt][3] *= al1;
            }
            __syncwarp();

#pragma unroll
            for (int ks = 0; ks < 8; ks++) {
                uint32_t pa[4];
                ldsm4(pa, a_base + ks * 32);
#pragma unroll
                for (int nt = 0; nt < 8; nt++) {
                    uint32_t b0 = Vs[(ks * 8 + tg) * VS_STRIDE + nt * 8 + gid];
                    uint32_t b1 = Vs[(ks * 8 + tg + 4) * VS_STRIDE + nt * 8 + gid];
                    mma_tf32(o[nt], pa, b0, b1);
                }
            }
        }
    }

    const float inv0 = 1.0f / l0;
    const float inv1 = 1.0f / l1;
#pragma unroll
    for (int nt = 0; nt < 8; nt++) {
        const int col = h * 64 + nt * 8 + 2 * tg;
        float2 v0, v1;
        v0.x = rnd_tf32(o[nt][0] * inv0); v0.y = rnd_tf32(o[nt][1] * inv0);
        v1.x = rnd_tf32(o[nt][2] * inv1); v1.y = rnd_tf32(o[nt][3] * inv1);
        *(float2*)&ctx[((size_t)r0g * BATCH + b) * DMODEL + col] = v0;
        *(float2*)&ctx[((size_t)r1g * BATCH + b) * DMODEL + col] = v1;
    }
}

// ---------------------------------------------------------------------------
extern "C" void kernel_launch(void* const* d_in, const int* in_sizes, int n_in,
                              void* d_out, int out_size)
{
    (void)in_sizes; (void)n_in; (void)out_size;
    const float* Q    = (const float*)d_in[0];
    const float* K    = (const float*)d_in[1];
    const float* V    = (const float*)d_in[2];
    const float* W_q  = (const float*)d_in[3];
    const float* b_q  = (const float*)d_in[4];
    const float* W_k  = (const float*)d_in[5];
    const float* b_k  = (const float*)d_in[6];
    const float* W_v  = (const float*)d_in[7];
    const float* b_v  = (const float*)d_in[8];
    const float* W_o  = (const float*)d_in[9];
    const float* b_o  = (const float*)d_in[10];
    const float* qcos = (const float*)d_in[11];
    const float* qsin = (const float*)d_in[12];
    const float* kcos = (const float*)d_in[13];
    const float* ksin = (const float*)d_in[14];
    float* out = (float*)d_out;

    float *gq, *gk, *gv, *gctx;
    cudaGetSymbolAddress((void**)&gq,   g_q);
    cudaGetSymbolAddress((void**)&gk,   g_k);
    cudaGetSymbolAddress((void**)&gv,   g_v);
    cudaGetSymbolAddress((void**)&gctx, g_ctx);

    cudaFuncSetAttribute(attn_tc,
                         cudaFuncAttributeMaxDynamicSharedMemorySize,
                         ATTN_SMEM_BYTES);
    cudaFuncSetAttribute(gemm_qkv,
                         cudaFuncAttributeMaxDynamicSharedMemorySize,
                         GEMM_SMEM_BYTES);
    cudaFuncSetAttribute(gemm_out,
                         cudaFuncAttributeMaxDynamicSharedMemorySize,
                         GEMM_SMEM_BYTES);

    dim3 pgrid(256, 4);
    preround_w<<<pgrid, 256>>>(W_q, W_k, W_v, W_o);

    dim3 qkv_grid(DMODEL / 128, NROWS / 128, 3);   // (8, 32, 3)
    gemm_qkv<<<qkv_grid, 256, GEMM_SMEM_BYTES>>>(
        Q, K, V, qcos, qsin, kcos, ksin, b_q, b_k, b_v);

    dim3 agrid(SLEN / QTILE, BATCH * NHEAD);       // (16, 32)
    attn_tc<<<agrid, 256, ATTN_SMEM_BYTES>>>(gq, gk, gv, gctx);

    dim3 ogrid(DMODEL / 128, NROWS / 128);         // (8, 32)
    gemm_out<<<ogrid, 256, GEMM_SMEM_BYTES>>>(b_o, out);
}